// round 14
// baseline (speedup 1.0000x reference)
#include <cuda_runtime.h>

// NormalizedCrossCorrelation via Parseval identity:
//   sum_k |X_k|^2 = nt * sum_n x_n^2  =>  Ex = DT * sum(x^2) + EPS
//   cc = sum(x*y) / sqrt(Ex*Ey), masked by max|x|>0, summed over all columns.
//
// x,y: [nt=4096, ncol=3072] row-major (columns contiguous).
//
// pass1: grid (6, 32), 512 threads = 4 time-slices x 128 col4 lanes.
//        Double-buffered streaming (8 LDG.128 in flight), smem slice-fold,
//        then slice-0 threads fold ACROSS blocks via L2 atomics into a 48 KB
//        per-column accumulator table g_acc[col4] = {sx2,sy2,sxy,mx(uint)}.
//        (max|x| via atomicMax on uint bits: valid since |x| >= 0.)
//        Triggers programmatic launch completion after the atomics.
// pass2: 6 blocks x 128 threads, PDL launch (ramps under pass1's tail,
//        cudaGridDependencySynchronize before reading). Thread = one col4:
//        read its fully-reduced 64B record, compute 4 cc's, block-reduce,
//        one atomicAdd into out, then zero its record for the next replay.

#define NT              4096
#define NCOL            3072
#define NC4             768          // NCOL / 4
#define SPLITS          32           // = pass1 grid.y
#define SLICES          4
#define COLS_PER_BLK    128
#define ROWS_PER_THREAD 32           // NT / SPLITS / SLICES
#define BLK1            (SLICES * COLS_PER_BLK)   // 512
#define COL_BLOCKS      6            // NC4 / COLS_PER_BLK
#define BLK2            128
#define GRID2           (NC4 / BLK2)   // 6
#define DT_CONST        0.001f
#define EPS_CONST       1e-10f

// Per-col4 accumulators: 4 float4 records {sx2, sy2, sxy, mx}.
// Zero-initialized at load; pass2 re-zeroes after reading (replay-safe).
__device__ float4 g_acc[NC4 * 4];

__device__ __forceinline__ void accum(const float4 xv, const float4 yv,
                                      float4& sx2, float4& sy2,
                                      float4& sxy, float4& mx) {
    sx2.x = fmaf(xv.x, xv.x, sx2.x);
    sx2.y = fmaf(xv.y, xv.y, sx2.y);
    sx2.z = fmaf(xv.z, xv.z, sx2.z);
    sx2.w = fmaf(xv.w, xv.w, sx2.w);
    sy2.x = fmaf(yv.x, yv.x, sy2.x);
    sy2.y = fmaf(yv.y, yv.y, sy2.y);
    sy2.z = fmaf(yv.z, yv.z, sy2.z);
    sy2.w = fmaf(yv.w, yv.w, sy2.w);
    sxy.x = fmaf(xv.x, yv.x, sxy.x);
    sxy.y = fmaf(xv.y, yv.y, sxy.y);
    sxy.z = fmaf(xv.z, yv.z, sxy.z);
    sxy.w = fmaf(xv.w, yv.w, sxy.w);
    mx.x = fmaxf(mx.x, fabsf(xv.x));
    mx.y = fmaxf(mx.y, fabsf(xv.y));
    mx.z = fmaxf(mx.z, fabsf(xv.z));
    mx.w = fmaxf(mx.w, fabsf(xv.w));
}

__global__ __launch_bounds__(BLK1, 2) void ncc_pass1(const float4* __restrict__ x,
                                                     const float4* __restrict__ y,
                                                     float* __restrict__ out) {
    if (blockIdx.x == 0 && blockIdx.y == 0 && threadIdx.x == 0)
        out[0] = 0.0f;   // pass2 gridDependencySynchronizes before touching out

    const int c     = threadIdx.x & (COLS_PER_BLK - 1);   // 0..127
    const int slice = threadIdx.x >> 7;                   // 0..3
    const int col4  = blockIdx.x * COLS_PER_BLK + c;      // 0..767
    const int row0  = blockIdx.y * (SLICES * ROWS_PER_THREAD) + slice * ROWS_PER_THREAD;

    float4 sx2 = make_float4(0.f, 0.f, 0.f, 0.f);
    float4 sy2 = make_float4(0.f, 0.f, 0.f, 0.f);
    float4 sxy = make_float4(0.f, 0.f, 0.f, 0.f);
    float4 mx  = make_float4(0.f, 0.f, 0.f, 0.f);

    const float4* xp = x + (size_t)row0 * NC4 + col4;
    const float4* yp = y + (size_t)row0 * NC4 + col4;

    // Double-buffered, 4 rows per stage: 8 LDG.128 always in flight.
    float4 xa0, xa1, xa2, xa3, ya0, ya1, ya2, ya3;
    xa0 = __ldcs(xp + 0 * NC4);
    xa1 = __ldcs(xp + 1 * NC4);
    xa2 = __ldcs(xp + 2 * NC4);
    xa3 = __ldcs(xp + 3 * NC4);
    ya0 = __ldcs(yp + 0 * NC4);
    ya1 = __ldcs(yp + 1 * NC4);
    ya2 = __ldcs(yp + 2 * NC4);
    ya3 = __ldcs(yp + 3 * NC4);

#pragma unroll
    for (int r = 4; r < ROWS_PER_THREAD; r += 4) {
        const float4* xn = xp + (size_t)r * NC4;
        const float4* yn = yp + (size_t)r * NC4;
        const float4 xb0 = __ldcs(xn + 0 * NC4);
        const float4 xb1 = __ldcs(xn + 1 * NC4);
        const float4 xb2 = __ldcs(xn + 2 * NC4);
        const float4 xb3 = __ldcs(xn + 3 * NC4);
        const float4 yb0 = __ldcs(yn + 0 * NC4);
        const float4 yb1 = __ldcs(yn + 1 * NC4);
        const float4 yb2 = __ldcs(yn + 2 * NC4);
        const float4 yb3 = __ldcs(yn + 3 * NC4);

        accum(xa0, ya0, sx2, sy2, sxy, mx);
        accum(xa1, ya1, sx2, sy2, sxy, mx);
        accum(xa2, ya2, sx2, sy2, sxy, mx);
        accum(xa3, ya3, sx2, sy2, sxy, mx);

        xa0 = xb0; xa1 = xb1; xa2 = xb2; xa3 = xb3;
        ya0 = yb0; ya1 = yb1; ya2 = yb2; ya3 = yb3;
    }
    accum(xa0, ya0, sx2, sy2, sxy, mx);
    accum(xa1, ya1, sx2, sy2, sxy, mx);
    accum(xa2, ya2, sx2, sy2, sxy, mx);
    accum(xa3, ya3, sx2, sy2, sxy, mx);

    // Intra-block reduction across the 4 time slices (smem, conflict-free).
    __shared__ float4 r_sx2[SLICES - 1][COLS_PER_BLK];
    __shared__ float4 r_sy2[SLICES - 1][COLS_PER_BLK];
    __shared__ float4 r_sxy[SLICES - 1][COLS_PER_BLK];
    __shared__ float4 r_mx [SLICES - 1][COLS_PER_BLK];

    if (slice > 0) {
        r_sx2[slice - 1][c] = sx2;
        r_sy2[slice - 1][c] = sy2;
        r_sxy[slice - 1][c] = sxy;
        r_mx [slice - 1][c] = mx;
    }
    __syncthreads();

    if (slice == 0) {
#pragma unroll
        for (int s = 0; s < SLICES - 1; s++) {
            const float4 a = r_sx2[s][c];
            const float4 b = r_sy2[s][c];
            const float4 d = r_sxy[s][c];
            const float4 m = r_mx [s][c];
            sx2.x += a.x; sx2.y += a.y; sx2.z += a.z; sx2.w += a.w;
            sy2.x += b.x; sy2.y += b.y; sy2.z += b.z; sy2.w += b.w;
            sxy.x += d.x; sxy.y += d.y; sxy.z += d.z; sxy.w += d.w;
            mx.x = fmaxf(mx.x, m.x); mx.y = fmaxf(mx.y, m.y);
            mx.z = fmaxf(mx.z, m.z); mx.w = fmaxf(mx.w, m.w);
        }

        // Cross-block fold in L2: 12 float adds + 4 uint maxes per col4.
        float* acc = (float*)&g_acc[col4 * 4];
        atomicAdd(acc + 0,  sx2.x);
        atomicAdd(acc + 1,  sx2.y);
        atomicAdd(acc + 2,  sx2.z);
        atomicAdd(acc + 3,  sx2.w);
        atomicAdd(acc + 4,  sy2.x);
        atomicAdd(acc + 5,  sy2.y);
        atomicAdd(acc + 6,  sy2.z);
        atomicAdd(acc + 7,  sy2.w);
        atomicAdd(acc + 8,  sxy.x);
        atomicAdd(acc + 9,  sxy.y);
        atomicAdd(acc + 10, sxy.z);
        atomicAdd(acc + 11, sxy.w);
        unsigned int* umx = (unsigned int*)(acc + 12);
        atomicMax(umx + 0, __float_as_uint(mx.x));  // |x| >= 0: uint order == float order
        atomicMax(umx + 1, __float_as_uint(mx.y));
        atomicMax(umx + 2, __float_as_uint(mx.z));
        atomicMax(umx + 3, __float_as_uint(mx.w));
    }

    // All accumulator updates issued: allow the PDL-dependent pass2 to proceed.
    cudaTriggerProgrammaticLaunchCompletion();
}

__global__ __launch_bounds__(BLK2) void ncc_pass2(float* __restrict__ out) {
    const int col4 = blockIdx.x * BLK2 + threadIdx.x;   // 0..767

    // Wait for pass1's grid (PDL edge) before reading accumulators / out.
    cudaGridDependencySynchronize();

    const float4 sx2 = g_acc[col4 * 4 + 0];
    const float4 sy2 = g_acc[col4 * 4 + 1];
    const float4 sxy = g_acc[col4 * 4 + 2];
    const float4 mxf = g_acc[col4 * 4 + 3];

    // Reset own record for the next graph replay (stream-ordered before it).
    const float4 z = make_float4(0.f, 0.f, 0.f, 0.f);
    g_acc[col4 * 4 + 0] = z;
    g_acc[col4 * 4 + 1] = z;
    g_acc[col4 * 4 + 2] = z;
    g_acc[col4 * 4 + 3] = z;

    float acc = 0.0f;
    {
        const float ex = DT_CONST * sx2.x + EPS_CONST;
        const float ey = DT_CONST * sy2.x + EPS_CONST;
        if (mxf.x > 0.f) acc += sxy.x / sqrtf(ex * ey);
    }
    {
        const float ex = DT_CONST * sx2.y + EPS_CONST;
        const float ey = DT_CONST * sy2.y + EPS_CONST;
        if (mxf.y > 0.f) acc += sxy.y / sqrtf(ex * ey);
    }
    {
        const float ex = DT_CONST * sx2.z + EPS_CONST;
        const float ey = DT_CONST * sy2.z + EPS_CONST;
        if (mxf.z > 0.f) acc += sxy.z / sqrtf(ex * ey);
    }
    {
        const float ex = DT_CONST * sx2.w + EPS_CONST;
        const float ey = DT_CONST * sy2.w + EPS_CONST;
        if (mxf.w > 0.f) acc += sxy.w / sqrtf(ex * ey);
    }

    // Block reduce (128 threads = 4 warps) -> one atomicAdd.
#pragma unroll
    for (int off = 16; off > 0; off >>= 1)
        acc += __shfl_down_sync(0xFFFFFFFFu, acc, off);

    __shared__ float warp_sums[BLK2 / 32];
    const int lane = threadIdx.x & 31;
    const int wid  = threadIdx.x >> 5;
    if (lane == 0) warp_sums[wid] = acc;
    __syncthreads();

    if (threadIdx.x == 0) {
        float v = warp_sums[0] + warp_sums[1] + warp_sums[2] + warp_sums[3];
        atomicAdd(out, v);
    }
}

extern "C" void kernel_launch(void* const* d_in, const int* in_sizes, int n_in,
                              void* d_out, int out_size) {
    const float4* x = (const float4*)d_in[0];
    const float4* y = (const float4*)d_in[1];
    float* out = (float*)d_out;

    ncc_pass1<<<dim3(COL_BLOCKS, SPLITS), BLK1>>>(x, y, out);

    // pass2 with Programmatic Dependent Launch: overlap its launch/ramp with
    // pass1's tail; correctness guarded by cudaGridDependencySynchronize().
    cudaLaunchAttribute attrs[1];
    attrs[0].id = cudaLaunchAttributeProgrammaticStreamSerialization;
    attrs[0].val.programmaticStreamSerializationAllowed = 1;

    cudaLaunchConfig_t cfg = {};
    cfg.gridDim  = dim3(GRID2, 1, 1);
    cfg.blockDim = dim3(BLK2, 1, 1);
    cfg.dynamicSmemBytes = 0;
    cfg.stream = 0;
    cfg.attrs = attrs;
    cfg.numAttrs = 1;

    cudaLaunchKernelEx(&cfg, ncc_pass2, out);
}